// round 6
// baseline (speedup 1.0000x reference)
#include <cuda_runtime.h>
#include <cuda_fp16.h>

#define D 64
#define NMAX 50000
#define EMAX 1250000
#define TILE_M 128
#define S_T 132

// ---------------- device scratch (no allocation allowed) ----------------
__device__ __half g_mh[NMAX * D];     // per-node message table (fp16)
__device__ int    g_hist[NMAX + 1];
__device__ int    g_off[NMAX + 1];    // CSR offsets
__device__ int    g_cursor[NMAX];
__device__ int    g_src_sorted[EMAX];

// Dynamic SMEM (floats): XH[64][S_T], W1s, W2s, b1s, b2s
#define SMEM_FLOATS (64 * S_T + 2 * 64 * 64 + 128)
#define SMEM_BYTES  (SMEM_FLOATS * 4)

// ===========================================================================
// Shared MLP body: assumes XH (transposed input tile) is staged; computes
// out_tile = relu(relu(X@W1+b1)@W2+b2) and writes to `out` (OutT rows).
// ===========================================================================
template <typename OutT>
__device__ __forceinline__ void mlp2_body(
    float* XH, const float* W1s, const float* W2s,
    const float* b1s, const float* b2s,
    OutT* __restrict__ out, int m0, int n, int tid)
{
    const int tn = tid & 15;
    const int tm = tid >> 4;
    const int cbase = tn * 4;
    const int mbase = tm * 8;

    float acc[4][8];

    // ================= Layer 1 =================
#pragma unroll
    for (int j = 0; j < 4; j++)
#pragma unroll
        for (int i = 0; i < 8; i++) acc[j][i] = 0.f;

#pragma unroll 8
    for (int k = 0; k < 64; k++) {
        const float4 a0 = *(const float4*)&XH[k * S_T + mbase];
        const float4 a1 = *(const float4*)&XH[k * S_T + mbase + 4];
        const float4 b  = *(const float4*)&W1s[k * 64 + cbase];
        const float a[8] = {a0.x, a0.y, a0.z, a0.w, a1.x, a1.y, a1.z, a1.w};
        const float bb[4] = {b.x, b.y, b.z, b.w};
#pragma unroll
        for (int j = 0; j < 4; j++)
#pragma unroll
            for (int i = 0; i < 8; i++)
                acc[j][i] = fmaf(a[i], bb[j], acc[j][i]);
    }

    __syncthreads();   // all reads of XH done before overwrite

#pragma unroll
    for (int j = 0; j < 4; j++) {
        const float bj = b1s[cbase + j];
#pragma unroll
        for (int i = 0; i < 8; i++) acc[j][i] = fmaxf(acc[j][i] + bj, 0.f);
        *(float4*)&XH[(cbase + j) * S_T + mbase] =
            make_float4(acc[j][0], acc[j][1], acc[j][2], acc[j][3]);
        *(float4*)&XH[(cbase + j) * S_T + mbase + 4] =
            make_float4(acc[j][4], acc[j][5], acc[j][6], acc[j][7]);
    }
    __syncthreads();

    // ================= Layer 2 =================
#pragma unroll
    for (int j = 0; j < 4; j++)
#pragma unroll
        for (int i = 0; i < 8; i++) acc[j][i] = 0.f;

#pragma unroll 8
    for (int k = 0; k < 64; k++) {
        const float4 a0 = *(const float4*)&XH[k * S_T + mbase];
        const float4 a1 = *(const float4*)&XH[k * S_T + mbase + 4];
        const float4 b  = *(const float4*)&W2s[k * 64 + cbase];
        const float a[8] = {a0.x, a0.y, a0.z, a0.w, a1.x, a1.y, a1.z, a1.w};
        const float bb[4] = {b.x, b.y, b.z, b.w};
#pragma unroll
        for (int j = 0; j < 4; j++)
#pragma unroll
            for (int i = 0; i < 8; i++)
                acc[j][i] = fmaf(a[i], bb[j], acc[j][i]);
    }

#pragma unroll
    for (int j = 0; j < 4; j++) {
        const float bj = b2s[cbase + j];
#pragma unroll
        for (int i = 0; i < 8; i++) acc[j][i] = fmaxf(acc[j][i] + bj, 0.f);
    }

#pragma unroll
    for (int i = 0; i < 8; i++) {
        const int m = m0 + mbase + i;
        if (m < n) {
            if constexpr (sizeof(OutT) == 4) {
                *(float4*)&out[(size_t)m * 64 + cbase] =
                    make_float4(acc[0][i], acc[1][i], acc[2][i], acc[3][i]);
            } else {
                __half2 h01 = __floats2half2_rn(acc[0][i], acc[1][i]);
                __half2 h23 = __floats2half2_rn(acc[2][i], acc[3][i]);
                uint2 u;
                u.x = *(unsigned int*)&h01;
                u.y = *(unsigned int*)&h23;
                *(uint2*)&out[(size_t)m * 64 + cbase] = u;
            }
        }
    }
}

__device__ __forceinline__ void stage_weights(
    const float* __restrict__ W1, const float* __restrict__ b1,
    const float* __restrict__ W2, const float* __restrict__ b2,
    float* W1s, float* W2s, float* b1s, float* b2s, int tid)
{
#pragma unroll
    for (int p = tid; p < 1024; p += 256) {
        ((float4*)W1s)[p] = ((const float4*)W1)[p];
        ((float4*)W2s)[p] = ((const float4*)W2)[p];
    }
    if (tid < 64) {
        b1s[tid] = b1[tid];
        b2s[tid] = b2[tid];
    }
}

// ===========================================================================
// K1: edge-message MLP (fp16 out) + fused dst histogram.
// Histogram REDs are fire-and-forget; they overlap the FMA-heavy MLP.
// ===========================================================================
__global__ __launch_bounds__(256, 3) void mlp1_hist_kernel(
    const float* __restrict__ in,
    const float* __restrict__ W1, const float* __restrict__ b1,
    const float* __restrict__ W2, const float* __restrict__ b2,
    __half* __restrict__ out, int n,
    const int4* __restrict__ dst4, int e4, int e, const int* __restrict__ dst)
{
    extern __shared__ float smem[];
    float* XH  = smem;
    float* W1s = XH + 64 * S_T;
    float* W2s = W1s + 4096;
    float* b1s = W2s + 4096;
    float* b2s = b1s + 64;

    const int tid = threadIdx.x;
    const int m0  = blockIdx.x * TILE_M;
    const int gtid = blockIdx.x * 256 + tid;
    const int gstride = gridDim.x * 256;

    // ---- fused histogram (independent of MLP data) ----
    for (int i = gtid; i < e4; i += gstride) {
        const int4 d = dst4[i];
        asm volatile("red.global.add.s32 [%0], 1;" :: "l"(&g_hist[d.x]) : "memory");
        asm volatile("red.global.add.s32 [%0], 1;" :: "l"(&g_hist[d.y]) : "memory");
        asm volatile("red.global.add.s32 [%0], 1;" :: "l"(&g_hist[d.z]) : "memory");
        asm volatile("red.global.add.s32 [%0], 1;" :: "l"(&g_hist[d.w]) : "memory");
    }
    if (gtid < e - e4 * 4) {
        asm volatile("red.global.add.s32 [%0], 1;"
                     :: "l"(&g_hist[dst[e4 * 4 + gtid]]) : "memory");
    }

    // ---- stage weights + X tile ----
    stage_weights(W1, b1, W2, b2, W1s, W2s, b1s, b2s, tid);
#pragma unroll
    for (int p = tid; p < TILE_M * 16; p += 256) {
        const int m  = p >> 4;
        const int kq = p & 15;
        float4 v = make_float4(0.f, 0.f, 0.f, 0.f);
        if (m0 + m < n) v = ((const float4*)in)[(size_t)(m0 + m) * 16 + kq];
        const int k = kq * 4;
        XH[(k + 0) * S_T + m] = v.x;
        XH[(k + 1) * S_T + m] = v.y;
        XH[(k + 2) * S_T + m] = v.z;
        XH[(k + 3) * S_T + m] = v.w;
    }
    __syncthreads();

    mlp2_body<__half>(XH, W1s, W2s, b1s, b2s, out, m0, n, tid);
}

// ===========================================================================
// K2: single-block exclusive scan of g_hist -> g_off, g_cursor.
// ===========================================================================
__global__ __launch_bounds__(1024) void scan_single_kernel(int n) {
    __shared__ int wsum[32];
    const int tid = threadIdx.x;
    const int lane = tid & 31;
    const int wid = tid >> 5;
    const int C = (n + 1023) / 1024;
    const int beg = tid * C;
    const int end = min(beg + C, n);

    int local = 0;
    for (int i = beg; i < end; i++) local += g_hist[i];

    // block exclusive scan of `local`
    int incl = local;
#pragma unroll
    for (int d = 1; d < 32; d <<= 1) {
        int t = __shfl_up_sync(0xffffffffu, incl, d);
        if (lane >= d) incl += t;
    }
    if (lane == 31) wsum[wid] = incl;
    __syncthreads();
    if (wid == 0) {
        int v = wsum[lane];
#pragma unroll
        for (int d = 1; d < 32; d <<= 1) {
            int t = __shfl_up_sync(0xffffffffu, v, d);
            if (lane >= d) v += t;
        }
        wsum[lane] = v;
    }
    __syncthreads();
    int run = incl - local + ((wid > 0) ? wsum[wid - 1] : 0);

    for (int i = beg; i < end; i++) {
        const int h = g_hist[i];
        g_off[i] = run;
        g_cursor[i] = run;
        run += h;
    }
    if (tid == 1023) g_off[n] = run;  // covers n: thread 1023's range ends at n
}

// ===========================================================================
// K3: reorder src by dst bucket (vectorized loads).
// ===========================================================================
__global__ __launch_bounds__(256) void reorder_kernel(
    const int4* __restrict__ src4, const int4* __restrict__ dst4,
    int e4, int e, const int* __restrict__ src, const int* __restrict__ dst)
{
    const int i = blockIdx.x * blockDim.x + threadIdx.x;
    if (i < e4) {
        const int4 s = src4[i];
        const int4 d = dst4[i];
        g_src_sorted[atomicAdd(&g_cursor[d.x], 1)] = s.x;
        g_src_sorted[atomicAdd(&g_cursor[d.y], 1)] = s.y;
        g_src_sorted[atomicAdd(&g_cursor[d.z], 1)] = s.z;
        g_src_sorted[atomicAdd(&g_cursor[d.w], 1)] = s.w;
    }
    if (i < e - e4 * 4) {
        const int r = e4 * 4 + i;
        g_src_sorted[atomicAdd(&g_cursor[dst[r]], 1)] = src[r];
    }
}

// ===========================================================================
// K4: fused CSR aggregation (fp16 gather, fp32 accum) -> SMEM tile -> MLP-2.
// Block handles 128 dst nodes: warp w aggregates nodes [w*16, w*16+16).
// ===========================================================================
__global__ __launch_bounds__(256, 3) void agg_mlp2_kernel(
    const __half2* __restrict__ m2,
    const float* __restrict__ U1, const float* __restrict__ c1,
    const float* __restrict__ U2, const float* __restrict__ c2,
    float* __restrict__ out, int n)
{
    extern __shared__ float smem[];
    float* XH  = smem;
    float* W1s = XH + 64 * S_T;
    float* W2s = W1s + 4096;
    float* b1s = W2s + 4096;
    float* b2s = b1s + 64;

    const int tid = threadIdx.x;
    const int m0  = blockIdx.x * TILE_M;
    const int warp = tid >> 5;
    const int lane = tid & 31;

    stage_weights(U1, c1, U2, c2, W1s, W2s, b1s, b2s, tid);

    // ---- aggregation into XH (transposed: XH[k][m_local]) ----
#pragma unroll 1
    for (int i = 0; i < 16; i++) {
        const int m_local = warp * 16 + i;
        const int node = m0 + m_local;
        float ax = 0.f, ay = 0.f;
        if (node < n) {
            const int s0 = __ldg(&g_off[node]);
            const int s1 = __ldg(&g_off[node + 1]);
            for (int base = s0; base < s1; base += 32) {
                const int cnt = min(32, s1 - base);
                int si = (lane < cnt) ? g_src_sorted[base + lane] : 0;
#pragma unroll 4
                for (int j = 0; j < cnt; j++) {
                    const int s = __shfl_sync(0xffffffffu, si, j);
                    const __half2 h = __ldg(&m2[(size_t)s * 32 + lane]);
                    const float2 v = __half22float2(h);
                    ax += v.x;
                    ay += v.y;
                }
            }
        }
        XH[(2 * lane) * S_T + m_local] = ax;
        XH[(2 * lane + 1) * S_T + m_local] = ay;
    }
    __syncthreads();

    mlp2_body<float>(XH, W1s, W2s, b1s, b2s, out, m0, n, tid);
}

// ---------------------------------------------------------------------------
extern "C" void kernel_launch(void* const* d_in, const int* in_sizes, int n_in,
                              void* d_out, int out_size) {
    const float* y   = (const float*)d_in[0];
    const int*   src = (const int*)d_in[1];
    const int*   dst = (const int*)d_in[2];
    const float* W1  = (const float*)d_in[3];
    const float* b1  = (const float*)d_in[4];
    const float* W2  = (const float*)d_in[5];
    const float* b2  = (const float*)d_in[6];
    const float* U1  = (const float*)d_in[7];
    const float* c1  = (const float*)d_in[8];
    const float* U2  = (const float*)d_in[9];
    const float* c2  = (const float*)d_in[10];
    float* out = (float*)d_out;

    const int n = in_sizes[0] / D;
    const int e = in_sizes[1];
    const int e4 = e / 4;

    __half* mh_ptr = nullptr;
    int*    hist_ptr = nullptr;
    cudaGetSymbolAddress((void**)&mh_ptr, g_mh);
    cudaGetSymbolAddress((void**)&hist_ptr, g_hist);

    cudaFuncSetAttribute(mlp1_hist_kernel,
                         cudaFuncAttributeMaxDynamicSharedMemorySize, SMEM_BYTES);
    cudaFuncSetAttribute(agg_mlp2_kernel,
                         cudaFuncAttributeMaxDynamicSharedMemorySize, SMEM_BYTES);

    const int mlp_blocks = (n + TILE_M - 1) / TILE_M;

    // 1) zero histogram
    cudaMemsetAsync(hist_ptr, 0, (size_t)(n + 1) * sizeof(int));

    // 2) edge-MLP message table + fused dst histogram
    mlp1_hist_kernel<<<mlp_blocks, 256, SMEM_BYTES>>>(
        y, W1, b1, W2, b2, mh_ptr, n, (const int4*)dst, e4, e, dst);

    // 3) CSR offsets (single-block scan)
    scan_single_kernel<<<1, 1024>>>(n);

    // 4) reorder src by dst
    {
        const int threads = e4 + 256;
        reorder_kernel<<<(threads + 255) / 256, 256>>>(
            (const int4*)src, (const int4*)dst, e4, e, src, dst);
    }

    // 5) fused aggregation + node-update MLP
    agg_mlp2_kernel<<<mlp_blocks, 256, SMEM_BYTES>>>(
        (const __half2*)mh_ptr, U1, c1, U2, c2, out, n);
}

// round 7
// speedup vs baseline: 1.3074x; 1.3074x over previous
#include <cuda_runtime.h>
#include <cuda_fp16.h>

#define D 64
#define NMAX 50000
#define EMAX 1250000
#define TILE_M 128
#define S_T 132

// ---------------- device scratch (no allocation allowed) ----------------
__device__ __half g_mh[NMAX * D];     // per-node message table (fp16)
__device__ float  g_z[NMAX * D];      // segment-sum result (fp32)
__device__ int    g_hist[NMAX + 1];
__device__ int    g_off[NMAX + 1];    // CSR offsets
__device__ int    g_cursor[NMAX];
__device__ int    g_src_sorted[EMAX];

// Dynamic SMEM (floats): XH[64][S_T], W1s, W2s, b1s, b2s
#define SMEM_FLOATS (64 * S_T + 2 * 64 * 64 + 128)
#define SMEM_BYTES  (SMEM_FLOATS * 4)

// ---------------------------------------------------------------------------
// Fused 2-layer MLP, register-blocked tiled GEMM (R4 champion version).
// ---------------------------------------------------------------------------
template <typename OutT>
__global__ __launch_bounds__(256, 3) void mlp2_tiled_kernel(
    const float* __restrict__ in,
    const float* __restrict__ W1, const float* __restrict__ b1,
    const float* __restrict__ W2, const float* __restrict__ b2,
    OutT* __restrict__ out, int n)
{
    extern __shared__ float smem[];
    float* XH  = smem;
    float* W1s = XH + 64 * S_T;
    float* W2s = W1s + 4096;
    float* b1s = W2s + 4096;
    float* b2s = b1s + 64;

    const int tid = threadIdx.x;
    const int m0  = blockIdx.x * TILE_M;

#pragma unroll
    for (int p = tid; p < 1024; p += 256) {
        ((float4*)W1s)[p] = ((const float4*)W1)[p];
        ((float4*)W2s)[p] = ((const float4*)W2)[p];
    }
    if (tid < 64) {
        b1s[tid] = b1[tid];
        b2s[tid] = b2[tid];
    }

#pragma unroll
    for (int p = tid; p < TILE_M * 16; p += 256) {
        const int m  = p >> 4;
        const int kq = p & 15;
        float4 v = make_float4(0.f, 0.f, 0.f, 0.f);
        if (m0 + m < n) v = ((const float4*)in)[(size_t)(m0 + m) * 16 + kq];
        const int k = kq * 4;
        XH[(k + 0) * S_T + m] = v.x;
        XH[(k + 1) * S_T + m] = v.y;
        XH[(k + 2) * S_T + m] = v.z;
        XH[(k + 3) * S_T + m] = v.w;
    }
    __syncthreads();

    const int tn = tid & 15;
    const int tm = tid >> 4;
    const int cbase = tn * 4;
    const int mbase = tm * 8;

    float acc[4][8];

    // ================= Layer 1 =================
#pragma unroll
    for (int j = 0; j < 4; j++)
#pragma unroll
        for (int i = 0; i < 8; i++) acc[j][i] = 0.f;

#pragma unroll 8
    for (int k = 0; k < 64; k++) {
        const float4 a0 = *(const float4*)&XH[k * S_T + mbase];
        const float4 a1 = *(const float4*)&XH[k * S_T + mbase + 4];
        const float4 b  = *(const float4*)&W1s[k * 64 + cbase];
        const float a[8] = {a0.x, a0.y, a0.z, a0.w, a1.x, a1.y, a1.z, a1.w};
        const float bb[4] = {b.x, b.y, b.z, b.w};
#pragma unroll
        for (int j = 0; j < 4; j++)
#pragma unroll
            for (int i = 0; i < 8; i++)
                acc[j][i] = fmaf(a[i], bb[j], acc[j][i]);
    }

    __syncthreads();

#pragma unroll
    for (int j = 0; j < 4; j++) {
        const float bj = b1s[cbase + j];
#pragma unroll
        for (int i = 0; i < 8; i++) acc[j][i] = fmaxf(acc[j][i] + bj, 0.f);
        *(float4*)&XH[(cbase + j) * S_T + mbase] =
            make_float4(acc[j][0], acc[j][1], acc[j][2], acc[j][3]);
        *(float4*)&XH[(cbase + j) * S_T + mbase + 4] =
            make_float4(acc[j][4], acc[j][5], acc[j][6], acc[j][7]);
    }
    __syncthreads();

    // ================= Layer 2 =================
#pragma unroll
    for (int j = 0; j < 4; j++)
#pragma unroll
        for (int i = 0; i < 8; i++) acc[j][i] = 0.f;

#pragma unroll 8
    for (int k = 0; k < 64; k++) {
        const float4 a0 = *(const float4*)&XH[k * S_T + mbase];
        const float4 a1 = *(const float4*)&XH[k * S_T + mbase + 4];
        const float4 b  = *(const float4*)&W2s[k * 64 + cbase];
        const float a[8] = {a0.x, a0.y, a0.z, a0.w, a1.x, a1.y, a1.z, a1.w};
        const float bb[4] = {b.x, b.y, b.z, b.w};
#pragma unroll
        for (int j = 0; j < 4; j++)
#pragma unroll
            for (int i = 0; i < 8; i++)
                acc[j][i] = fmaf(a[i], bb[j], acc[j][i]);
    }

#pragma unroll
    for (int j = 0; j < 4; j++) {
        const float bj = b2s[cbase + j];
#pragma unroll
        for (int i = 0; i < 8; i++) acc[j][i] = fmaxf(acc[j][i] + bj, 0.f);
    }

#pragma unroll
    for (int i = 0; i < 8; i++) {
        const int m = m0 + mbase + i;
        if (m < n) {
            if constexpr (sizeof(OutT) == 4) {
                *(float4*)&out[(size_t)m * 64 + cbase] =
                    make_float4(acc[0][i], acc[1][i], acc[2][i], acc[3][i]);
            } else {
                __half2 h01 = __floats2half2_rn(acc[0][i], acc[1][i]);
                __half2 h23 = __floats2half2_rn(acc[2][i], acc[3][i]);
                uint2 u;
                u.x = *(unsigned int*)&h01;
                u.y = *(unsigned int*)&h23;
                *(uint2*)&out[(size_t)m * 64 + cbase] = u;
            }
        }
    }
}

// ---------------------------------------------------------------------------
// Histogram of dst (vectorized int4 loads).
// ---------------------------------------------------------------------------
__global__ __launch_bounds__(256) void hist_kernel(const int4* __restrict__ dst4,
                                                   int e4, int e,
                                                   const int* __restrict__ dst) {
    const int i = blockIdx.x * blockDim.x + threadIdx.x;
    if (i < e4) {
        const int4 d = dst4[i];
        asm volatile("red.global.add.s32 [%0], 1;" :: "l"(&g_hist[d.x]) : "memory");
        asm volatile("red.global.add.s32 [%0], 1;" :: "l"(&g_hist[d.y]) : "memory");
        asm volatile("red.global.add.s32 [%0], 1;" :: "l"(&g_hist[d.z]) : "memory");
        asm volatile("red.global.add.s32 [%0], 1;" :: "l"(&g_hist[d.w]) : "memory");
    }
    if (i < e - e4 * 4) {
        const int r = e4 * 4 + i;
        asm volatile("red.global.add.s32 [%0], 1;" :: "l"(&g_hist[dst[r]]) : "memory");
    }
}

// ---------------------------------------------------------------------------
// Single-block exclusive scan of g_hist -> g_off, g_cursor (one launch).
// ---------------------------------------------------------------------------
__global__ __launch_bounds__(1024) void scan_single_kernel(int n) {
    __shared__ int wsum[32];
    const int tid = threadIdx.x;
    const int lane = tid & 31;
    const int wid = tid >> 5;
    const int C = (n + 1023) / 1024;
    const int beg = min(tid * C, n);
    const int end = min(beg + C, n);

    int local = 0;
    for (int i = beg; i < end; i++) local += g_hist[i];

    int incl = local;
#pragma unroll
    for (int d = 1; d < 32; d <<= 1) {
        int t = __shfl_up_sync(0xffffffffu, incl, d);
        if (lane >= d) incl += t;
    }
    if (lane == 31) wsum[wid] = incl;
    __syncthreads();
    if (wid == 0) {
        int v = wsum[lane];
#pragma unroll
        for (int d = 1; d < 32; d <<= 1) {
            int t = __shfl_up_sync(0xffffffffu, v, d);
            if (lane >= d) v += t;
        }
        wsum[lane] = v;
    }
    __syncthreads();
    int run = incl - local + ((wid > 0) ? wsum[wid - 1] : 0);

    for (int i = beg; i < end; i++) {
        const int h = g_hist[i];
        g_off[i] = run;
        g_cursor[i] = run;
        run += h;
    }
    if (tid == 1023) g_off[n] = run;
}

// ---------------------------------------------------------------------------
// Reorder src by dst bucket (vectorized loads).
// ---------------------------------------------------------------------------
__global__ __launch_bounds__(256) void reorder_kernel(
    const int4* __restrict__ src4, const int4* __restrict__ dst4,
    int e4, int e, const int* __restrict__ src, const int* __restrict__ dst)
{
    const int i = blockIdx.x * blockDim.x + threadIdx.x;
    if (i < e4) {
        const int4 s = src4[i];
        const int4 d = dst4[i];
        g_src_sorted[atomicAdd(&g_cursor[d.x], 1)] = s.x;
        g_src_sorted[atomicAdd(&g_cursor[d.y], 1)] = s.y;
        g_src_sorted[atomicAdd(&g_cursor[d.z], 1)] = s.z;
        g_src_sorted[atomicAdd(&g_cursor[d.w], 1)] = s.w;
    }
    if (i < e - e4 * 4) {
        const int r = e4 * 4 + i;
        g_src_sorted[atomicAdd(&g_cursor[dst[r]], 1)] = src[r];
    }
}

// ---------------------------------------------------------------------------
// CSR aggregation: warp per node, fp16 gather, fp32 accumulation (R4 champion).
// ---------------------------------------------------------------------------
__global__ __launch_bounds__(256) void aggregate_kernel(
    const __half2* __restrict__ m2, float2* __restrict__ z2, int n)
{
    const int warp = (blockIdx.x * 256 + threadIdx.x) >> 5;
    const int lane = threadIdx.x & 31;
    if (warp >= n) return;

    const int s0 = g_off[warp];
    const int s1 = g_off[warp + 1];

    float ax = 0.f, ay = 0.f;
    for (int base = s0; base < s1; base += 32) {
        const int cnt = min(32, s1 - base);
        int si = (lane < cnt) ? g_src_sorted[base + lane] : 0;
#pragma unroll 4
        for (int j = 0; j < cnt; j++) {
            const int s = __shfl_sync(0xffffffffu, si, j);
            const __half2 h = __ldg(&m2[(size_t)s * 32 + lane]);
            const float2 v = __half22float2(h);
            ax += v.x;
            ay += v.y;
        }
    }
    float2 o;
    o.x = ax;
    o.y = ay;
    z2[(size_t)warp * 32 + lane] = o;
}

// ---------------------------------------------------------------------------
extern "C" void kernel_launch(void* const* d_in, const int* in_sizes, int n_in,
                              void* d_out, int out_size) {
    const float* y   = (const float*)d_in[0];
    const int*   src = (const int*)d_in[1];
    const int*   dst = (const int*)d_in[2];
    const float* W1  = (const float*)d_in[3];
    const float* b1  = (const float*)d_in[4];
    const float* W2  = (const float*)d_in[5];
    const float* b2  = (const float*)d_in[6];
    const float* U1  = (const float*)d_in[7];
    const float* c1  = (const float*)d_in[8];
    const float* U2  = (const float*)d_in[9];
    const float* c2  = (const float*)d_in[10];
    float* out = (float*)d_out;

    const int n = in_sizes[0] / D;
    const int e = in_sizes[1];
    const int e4 = e / 4;

    __half* mh_ptr = nullptr;
    float*  z_ptr  = nullptr;
    int*    hist_ptr = nullptr;
    cudaGetSymbolAddress((void**)&mh_ptr, g_mh);
    cudaGetSymbolAddress((void**)&z_ptr, g_z);
    cudaGetSymbolAddress((void**)&hist_ptr, g_hist);

    cudaFuncSetAttribute(mlp2_tiled_kernel<__half>,
                         cudaFuncAttributeMaxDynamicSharedMemorySize, SMEM_BYTES);
    cudaFuncSetAttribute(mlp2_tiled_kernel<float>,
                         cudaFuncAttributeMaxDynamicSharedMemorySize, SMEM_BYTES);

    static cudaStream_t s_side = ([] {
        cudaStream_t s;
        cudaStreamCreateWithFlags(&s, cudaStreamNonBlocking);
        return s;
    })();
    static cudaEvent_t ev_fork = ([] {
        cudaEvent_t ev;
        cudaEventCreateWithFlags(&ev, cudaEventDisableTiming);
        return ev;
    })();
    static cudaEvent_t ev_join = ([] {
        cudaEvent_t ev;
        cudaEventCreateWithFlags(&ev, cudaEventDisableTiming);
        return ev;
    })();

    const int mlp_blocks = (n + TILE_M - 1) / TILE_M;
    const int ev_threads = e4 + 256;  // covers vector part and remainder

    // ---- fork: sort pipeline on side stream (depends only on src/dst) ----
    cudaEventRecord(ev_fork, (cudaStream_t)0);
    cudaStreamWaitEvent(s_side, ev_fork, 0);

    cudaMemsetAsync(hist_ptr, 0, (size_t)(n + 1) * sizeof(int), s_side);
    hist_kernel<<<(ev_threads + 255) / 256, 256, 0, s_side>>>(
        (const int4*)dst, e4, e, dst);
    scan_single_kernel<<<1, 1024, 0, s_side>>>(n);
    reorder_kernel<<<(ev_threads + 255) / 256, 256, 0, s_side>>>(
        (const int4*)src, (const int4*)dst, e4, e, src, dst);
    cudaEventRecord(ev_join, s_side);

    // ---- main stream: edge-MLP message table (fp16 out), overlapped ----
    mlp2_tiled_kernel<__half><<<mlp_blocks, 256, SMEM_BYTES>>>(
        y, W1, b1, W2, b2, mh_ptr, n);

    // ---- join, then aggregate + node MLP ----
    cudaStreamWaitEvent((cudaStream_t)0, ev_join, 0);
    {
        const int blocks = (n * 32 + 255) / 256;
        aggregate_kernel<<<blocks, 256>>>((const __half2*)mh_ptr, (float2*)z_ptr, n);
    }
    mlp2_tiled_kernel<float><<<mlp_blocks, 256, SMEM_BYTES>>>(
        z_ptr, U1, c1, U2, c2, out, n);
}

// round 8
// speedup vs baseline: 1.9751x; 1.5107x over previous
#include <cuda_runtime.h>
#include <cuda_fp16.h>

#define D 64
#define NMAX 50000
#define EMAX 1250000
#define TILE_M 128
#define S_T 132
#define SCAN_CHUNK 1024

// ---------------- device scratch (no allocation allowed) ----------------
__device__ __half g_mh[NMAX * D];     // per-node message table (fp16)
__device__ float  g_z[NMAX * D];      // segment-sum result (fp32)
__device__ int    g_hist[NMAX + 1];
__device__ int    g_off[NMAX + 1];    // CSR offsets
__device__ int    g_cursor[NMAX];
__device__ int    g_bsum[64];         // per-chunk sums
__device__ int    g_src_sorted[EMAX];

// Dynamic SMEM (floats): XH[64][S_T], W1s, W2s, b1s, b2s
#define SMEM_FLOATS (64 * S_T + 2 * 64 * 64 + 128)
#define SMEM_BYTES  (SMEM_FLOATS * 4)

// ---------------------------------------------------------------------------
// Fused 2-layer MLP, register-blocked tiled GEMM (R4 champion version).
// ---------------------------------------------------------------------------
template <typename OutT>
__global__ __launch_bounds__(256, 3) void mlp2_tiled_kernel(
    const float* __restrict__ in,
    const float* __restrict__ W1, const float* __restrict__ b1,
    const float* __restrict__ W2, const float* __restrict__ b2,
    OutT* __restrict__ out, int n)
{
    extern __shared__ float smem[];
    float* XH  = smem;
    float* W1s = XH + 64 * S_T;
    float* W2s = W1s + 4096;
    float* b1s = W2s + 4096;
    float* b2s = b1s + 64;

    const int tid = threadIdx.x;
    const int m0  = blockIdx.x * TILE_M;

#pragma unroll
    for (int p = tid; p < 1024; p += 256) {
        ((float4*)W1s)[p] = ((const float4*)W1)[p];
        ((float4*)W2s)[p] = ((const float4*)W2)[p];
    }
    if (tid < 64) {
        b1s[tid] = b1[tid];
        b2s[tid] = b2[tid];
    }

#pragma unroll
    for (int p = tid; p < TILE_M * 16; p += 256) {
        const int m  = p >> 4;
        const int kq = p & 15;
        float4 v = make_float4(0.f, 0.f, 0.f, 0.f);
        if (m0 + m < n) v = ((const float4*)in)[(size_t)(m0 + m) * 16 + kq];
        const int k = kq * 4;
        XH[(k + 0) * S_T + m] = v.x;
        XH[(k + 1) * S_T + m] = v.y;
        XH[(k + 2) * S_T + m] = v.z;
        XH[(k + 3) * S_T + m] = v.w;
    }
    __syncthreads();

    const int tn = tid & 15;
    const int tm = tid >> 4;
    const int cbase = tn * 4;
    const int mbase = tm * 8;

    float acc[4][8];

    // ================= Layer 1 =================
#pragma unroll
    for (int j = 0; j < 4; j++)
#pragma unroll
        for (int i = 0; i < 8; i++) acc[j][i] = 0.f;

#pragma unroll 8
    for (int k = 0; k < 64; k++) {
        const float4 a0 = *(const float4*)&XH[k * S_T + mbase];
        const float4 a1 = *(const float4*)&XH[k * S_T + mbase + 4];
        const float4 b  = *(const float4*)&W1s[k * 64 + cbase];
        const float a[8] = {a0.x, a0.y, a0.z, a0.w, a1.x, a1.y, a1.z, a1.w};
        const float bb[4] = {b.x, b.y, b.z, b.w};
#pragma unroll
        for (int j = 0; j < 4; j++)
#pragma unroll
            for (int i = 0; i < 8; i++)
                acc[j][i] = fmaf(a[i], bb[j], acc[j][i]);
    }

    __syncthreads();

#pragma unroll
    for (int j = 0; j < 4; j++) {
        const float bj = b1s[cbase + j];
#pragma unroll
        for (int i = 0; i < 8; i++) acc[j][i] = fmaxf(acc[j][i] + bj, 0.f);
        *(float4*)&XH[(cbase + j) * S_T + mbase] =
            make_float4(acc[j][0], acc[j][1], acc[j][2], acc[j][3]);
        *(float4*)&XH[(cbase + j) * S_T + mbase + 4] =
            make_float4(acc[j][4], acc[j][5], acc[j][6], acc[j][7]);
    }
    __syncthreads();

    // ================= Layer 2 =================
#pragma unroll
    for (int j = 0; j < 4; j++)
#pragma unroll
        for (int i = 0; i < 8; i++) acc[j][i] = 0.f;

#pragma unroll 8
    for (int k = 0; k < 64; k++) {
        const float4 a0 = *(const float4*)&XH[k * S_T + mbase];
        const float4 a1 = *(const float4*)&XH[k * S_T + mbase + 4];
        const float4 b  = *(const float4*)&W2s[k * 64 + cbase];
        const float a[8] = {a0.x, a0.y, a0.z, a0.w, a1.x, a1.y, a1.z, a1.w};
        const float bb[4] = {b.x, b.y, b.z, b.w};
#pragma unroll
        for (int j = 0; j < 4; j++)
#pragma unroll
            for (int i = 0; i < 8; i++)
                acc[j][i] = fmaf(a[i], bb[j], acc[j][i]);
    }

#pragma unroll
    for (int j = 0; j < 4; j++) {
        const float bj = b2s[cbase + j];
#pragma unroll
        for (int i = 0; i < 8; i++) acc[j][i] = fmaxf(acc[j][i] + bj, 0.f);
    }

#pragma unroll
    for (int i = 0; i < 8; i++) {
        const int m = m0 + mbase + i;
        if (m < n) {
            if constexpr (sizeof(OutT) == 4) {
                *(float4*)&out[(size_t)m * 64 + cbase] =
                    make_float4(acc[0][i], acc[1][i], acc[2][i], acc[3][i]);
            } else {
                __half2 h01 = __floats2half2_rn(acc[0][i], acc[1][i]);
                __half2 h23 = __floats2half2_rn(acc[2][i], acc[3][i]);
                uint2 u;
                u.x = *(unsigned int*)&h01;
                u.y = *(unsigned int*)&h23;
                *(uint2*)&out[(size_t)m * 64 + cbase] = u;
            }
        }
    }
}

// ---------------------------------------------------------------------------
// Histogram of dst (vectorized int4 loads).
// ---------------------------------------------------------------------------
__global__ __launch_bounds__(256) void hist_kernel(const int4* __restrict__ dst4,
                                                   int e4, int e,
                                                   const int* __restrict__ dst) {
    const int i = blockIdx.x * blockDim.x + threadIdx.x;
    if (i < e4) {
        const int4 d = dst4[i];
        asm volatile("red.global.add.s32 [%0], 1;" :: "l"(&g_hist[d.x]) : "memory");
        asm volatile("red.global.add.s32 [%0], 1;" :: "l"(&g_hist[d.y]) : "memory");
        asm volatile("red.global.add.s32 [%0], 1;" :: "l"(&g_hist[d.z]) : "memory");
        asm volatile("red.global.add.s32 [%0], 1;" :: "l"(&g_hist[d.w]) : "memory");
    }
    if (i < e - e4 * 4) {
        const int r = e4 * 4 + i;
        asm volatile("red.global.add.s32 [%0], 1;" :: "l"(&g_hist[dst[r]]) : "memory");
    }
}

__device__ __forceinline__ int warp_incl_scan(int v, int lane) {
#pragma unroll
    for (int d = 1; d < 32; d <<= 1) {
        int t = __shfl_up_sync(0xffffffffu, v, d);
        if (lane >= d) v += t;
    }
    return v;
}

// ---------------------------------------------------------------------------
// Scan kernel A: per-chunk sums (49 blocks of 1024; coalesced).
// ---------------------------------------------------------------------------
__global__ __launch_bounds__(SCAN_CHUNK) void scan_sums_kernel(int n) {
    __shared__ int wsum[32];
    const int g = blockIdx.x * SCAN_CHUNK + threadIdx.x;
    const int lane = threadIdx.x & 31;
    const int wid = threadIdx.x >> 5;
    int x = (g < n) ? g_hist[g] : 0;
#pragma unroll
    for (int d = 16; d > 0; d >>= 1) x += __shfl_down_sync(0xffffffffu, x, d);
    if (lane == 0) wsum[wid] = x;
    __syncthreads();
    if (wid == 0) {
        int v = wsum[lane];
#pragma unroll
        for (int d = 16; d > 0; d >>= 1) v += __shfl_down_sync(0xffffffffu, v, d);
        if (lane == 0) g_bsum[blockIdx.x] = v;
    }
}

// ---------------------------------------------------------------------------
// Scan kernel B: each block computes its own prefix from the <=64 chunk sums
// (warp 0, registers) then scans its 1024-element chunk. One launch, 49 blocks.
// ---------------------------------------------------------------------------
__global__ __launch_bounds__(SCAN_CHUNK) void scan_final_kernel(int n, int nb) {
    __shared__ int wsum[32];
    __shared__ int s_block_prefix;

    const int b = blockIdx.x;
    const int tid = threadIdx.x;
    const int lane = tid & 31;
    const int wid = tid >> 5;
    const int g = b * SCAN_CHUNK + tid;

    // warp 0: exclusive prefix of chunk sums at index b
    if (wid == 0) {
        int v0 = (lane < nb) ? g_bsum[lane] : 0;
        int v1 = (lane + 32 < nb) ? g_bsum[lane + 32] : 0;
        int s0 = warp_incl_scan(v0, lane);
        const int tot0 = __shfl_sync(0xffffffffu, s0, 31);
        int s1 = warp_incl_scan(v1, lane) + tot0;
        const int idx = b - 1;
        const int a = __shfl_sync(0xffffffffu, s0, idx & 31);
        const int c = __shfl_sync(0xffffffffu, s1, idx & 31);
        if (lane == 0)
            s_block_prefix = (idx < 0) ? 0 : ((idx < 32) ? a : c);
    }
    __syncthreads();

    int x = (g < n) ? g_hist[g] : 0;
    int incl = warp_incl_scan(x, lane);
    if (lane == 31) wsum[wid] = incl;
    __syncthreads();
    if (wid == 0) wsum[lane] = warp_incl_scan(wsum[lane], lane);
    __syncthreads();
    const int excl = incl - x + ((wid > 0) ? wsum[wid - 1] : 0) + s_block_prefix;
    if (g < n) {
        g_off[g] = excl;
        g_cursor[g] = excl;
    }
    if (g == n - 1) g_off[n] = excl + x;
}

// ---------------------------------------------------------------------------
// Reorder src by dst bucket (vectorized loads).
// ---------------------------------------------------------------------------
__global__ __launch_bounds__(256) void reorder_kernel(
    const int4* __restrict__ src4, const int4* __restrict__ dst4,
    int e4, int e, const int* __restrict__ src, const int* __restrict__ dst)
{
    const int i = blockIdx.x * blockDim.x + threadIdx.x;
    if (i < e4) {
        const int4 s = src4[i];
        const int4 d = dst4[i];
        g_src_sorted[atomicAdd(&g_cursor[d.x], 1)] = s.x;
        g_src_sorted[atomicAdd(&g_cursor[d.y], 1)] = s.y;
        g_src_sorted[atomicAdd(&g_cursor[d.z], 1)] = s.z;
        g_src_sorted[atomicAdd(&g_cursor[d.w], 1)] = s.w;
    }
    if (i < e - e4 * 4) {
        const int r = e4 * 4 + i;
        g_src_sorted[atomicAdd(&g_cursor[dst[r]], 1)] = src[r];
    }
}

// ---------------------------------------------------------------------------
// CSR aggregation: warp per node, fp16 gather, fp32 accumulation.
// ---------------------------------------------------------------------------
__global__ __launch_bounds__(256) void aggregate_kernel(
    const __half2* __restrict__ m2, float2* __restrict__ z2, int n)
{
    const int warp = (blockIdx.x * 256 + threadIdx.x) >> 5;
    const int lane = threadIdx.x & 31;
    if (warp >= n) return;

    const int s0 = g_off[warp];
    const int s1 = g_off[warp + 1];

    float ax = 0.f, ay = 0.f;
    for (int base = s0; base < s1; base += 32) {
        const int cnt = min(32, s1 - base);
        int si = (lane < cnt) ? g_src_sorted[base + lane] : 0;
#pragma unroll 4
        for (int j = 0; j < cnt; j++) {
            const int s = __shfl_sync(0xffffffffu, si, j);
            const __half2 h = __ldg(&m2[(size_t)s * 32 + lane]);
            const float2 v = __half22float2(h);
            ax += v.x;
            ay += v.y;
        }
    }
    float2 o;
    o.x = ax;
    o.y = ay;
    z2[(size_t)warp * 32 + lane] = o;
}

// ---------------------------------------------------------------------------
extern "C" void kernel_launch(void* const* d_in, const int* in_sizes, int n_in,
                              void* d_out, int out_size) {
    const float* y   = (const float*)d_in[0];
    const int*   src = (const int*)d_in[1];
    const int*   dst = (const int*)d_in[2];
    const float* W1  = (const float*)d_in[3];
    const float* b1  = (const float*)d_in[4];
    const float* W2  = (const float*)d_in[5];
    const float* b2  = (const float*)d_in[6];
    const float* U1  = (const float*)d_in[7];
    const float* c1  = (const float*)d_in[8];
    const float* U2  = (const float*)d_in[9];
    const float* c2  = (const float*)d_in[10];
    float* out = (float*)d_out;

    const int n = in_sizes[0] / D;
    const int e = in_sizes[1];
    const int e4 = e / 4;

    __half* mh_ptr = nullptr;
    float*  z_ptr  = nullptr;
    int*    hist_ptr = nullptr;
    cudaGetSymbolAddress((void**)&mh_ptr, g_mh);
    cudaGetSymbolAddress((void**)&z_ptr, g_z);
    cudaGetSymbolAddress((void**)&hist_ptr, g_hist);

    cudaFuncSetAttribute(mlp2_tiled_kernel<__half>,
                         cudaFuncAttributeMaxDynamicSharedMemorySize, SMEM_BYTES);
    cudaFuncSetAttribute(mlp2_tiled_kernel<float>,
                         cudaFuncAttributeMaxDynamicSharedMemorySize, SMEM_BYTES);

    static cudaStream_t s_side = ([] {
        cudaStream_t s;
        cudaStreamCreateWithFlags(&s, cudaStreamNonBlocking);
        return s;
    })();
    static cudaEvent_t ev_fork = ([] {
        cudaEvent_t ev;
        cudaEventCreateWithFlags(&ev, cudaEventDisableTiming);
        return ev;
    })();
    static cudaEvent_t ev_join = ([] {
        cudaEvent_t ev;
        cudaEventCreateWithFlags(&ev, cudaEventDisableTiming);
        return ev;
    })();

    const int mlp_blocks = (n + TILE_M - 1) / TILE_M;
    const int nb = (n + SCAN_CHUNK - 1) / SCAN_CHUNK;
    const int ev_threads = e4 + 256;

    // ---- fork: sort pipeline on side stream (depends only on src/dst) ----
    cudaEventRecord(ev_fork, (cudaStream_t)0);
    cudaStreamWaitEvent(s_side, ev_fork, 0);

    cudaMemsetAsync(hist_ptr, 0, (size_t)(n + 1) * sizeof(int), s_side);
    hist_kernel<<<(ev_threads + 255) / 256, 256, 0, s_side>>>(
        (const int4*)dst, e4, e, dst);
    scan_sums_kernel<<<nb, SCAN_CHUNK, 0, s_side>>>(n);
    scan_final_kernel<<<nb, SCAN_CHUNK, 0, s_side>>>(n, nb);
    reorder_kernel<<<(ev_threads + 255) / 256, 256, 0, s_side>>>(
        (const int4*)src, (const int4*)dst, e4, e, src, dst);
    cudaEventRecord(ev_join, s_side);

    // ---- main stream: edge-MLP message table (fp16 out) ----
    mlp2_tiled_kernel<__half><<<mlp_blocks, 256, SMEM_BYTES>>>(
        y, W1, b1, W2, b2, mh_ptr, n);

    // ---- join, then aggregate + node MLP ----
    cudaStreamWaitEvent((cudaStream_t)0, ev_join, 0);
    {
        const int blocks = (n * 32 + 255) / 256;
        aggregate_kernel<<<blocks, 256>>>((const __half2*)mh_ptr, (float2*)z_ptr, n);
    }
    mlp2_tiled_kernel<float><<<mlp_blocks, 256, SMEM_BYTES>>>(
        z_ptr, U1, c1, U2, c2, out, n);
}

// round 9
// speedup vs baseline: 2.1362x; 1.0816x over previous
#include <cuda_runtime.h>
#include <cuda_fp16.h>

#define D 64
#define NMAX 50000
#define EMAX 1250000
#define TILE_M 128
#define S_T 132
#define SCAN_CHUNK 1024

// ---------------- device scratch (no allocation allowed) ----------------
__device__ __half g_mh[NMAX * D];     // per-node message table (fp16)
__device__ float  g_z[NMAX * D];      // segment-sum result (fp32)
__device__ int    g_hist[NMAX + 1];
__device__ int    g_off[NMAX + 1];    // CSR offsets
__device__ int    g_cursor[NMAX];
__device__ int    g_bsum[64];         // per-chunk sums
__device__ int    g_boff[64];         // per-chunk offsets
__device__ int    g_src_sorted[EMAX];

// Dynamic SMEM (floats): XH[64][S_T], W1s, W2s, b1s, b2s
#define SMEM_FLOATS (64 * S_T + 2 * 64 * 64 + 128)
#define SMEM_BYTES  (SMEM_FLOATS * 4)

// ---------------- packed fp32x2 helpers (sm_100+/sm_103a) ----------------
__device__ __forceinline__ unsigned long long dup_f32x2(float x) {
    unsigned long long r;
    asm("mov.b64 %0, {%1, %1};" : "=l"(r) : "f"(x));
    return r;
}
__device__ __forceinline__ unsigned long long pack_f32x2(float x, float y) {
    unsigned long long r;
    asm("mov.b64 %0, {%1, %2};" : "=l"(r) : "f"(x), "f"(y));
    return r;
}
__device__ __forceinline__ void unpack_f32x2(unsigned long long v, float& x, float& y) {
    asm("mov.b64 {%0, %1}, %2;" : "=f"(x), "=f"(y) : "l"(v));
}
// d = a * b + d   (two independent fp32 FMAs, .rn — identical rounding to fmaf)
#define FMA2(d, a, b) \
    asm("fma.rn.f32x2 %0, %1, %2, %0;" : "+l"(d) : "l"(a), "l"(b))

// ---------------------------------------------------------------------------
// Fused 2-layer MLP, register-blocked tiled GEMM with packed f32x2 FMAs.
// Block: 256 threads, 128-node tile. Thread tile: 8 nodes x 4 cols.
// Pairs are over the node dimension (natural register pairs from float4 LDS).
// ---------------------------------------------------------------------------
template <typename OutT>
__global__ __launch_bounds__(256, 3) void mlp2_tiled_kernel(
    const float* __restrict__ in,
    const float* __restrict__ W1, const float* __restrict__ b1,
    const float* __restrict__ W2, const float* __restrict__ b2,
    OutT* __restrict__ out, int n)
{
    extern __shared__ float smem[];
    float* XH  = smem;
    float* W1s = XH + 64 * S_T;
    float* W2s = W1s + 4096;
    float* b1s = W2s + 4096;
    float* b2s = b1s + 64;

    const int tid = threadIdx.x;
    const int m0  = blockIdx.x * TILE_M;

#pragma unroll
    for (int p = tid; p < 1024; p += 256) {
        ((float4*)W1s)[p] = ((const float4*)W1)[p];
        ((float4*)W2s)[p] = ((const float4*)W2)[p];
    }
    if (tid < 64) {
        b1s[tid] = b1[tid];
        b2s[tid] = b2[tid];
    }

#pragma unroll
    for (int p = tid; p < TILE_M * 16; p += 256) {
        const int m  = p >> 4;
        const int kq = p & 15;
        float4 v = make_float4(0.f, 0.f, 0.f, 0.f);
        if (m0 + m < n) v = ((const float4*)in)[(size_t)(m0 + m) * 16 + kq];
        const int k = kq * 4;
        XH[(k + 0) * S_T + m] = v.x;
        XH[(k + 1) * S_T + m] = v.y;
        XH[(k + 2) * S_T + m] = v.z;
        XH[(k + 3) * S_T + m] = v.w;
    }
    __syncthreads();

    const int tn = tid & 15;
    const int tm = tid >> 4;
    const int cbase = tn * 4;
    const int mbase = tm * 8;

    unsigned long long acc2[4][4];   // [col][node-pair]
    float acc[4][8];

    // ================= Layer 1 =================
#pragma unroll
    for (int j = 0; j < 4; j++)
#pragma unroll
        for (int ii = 0; ii < 4; ii++) acc2[j][ii] = 0ULL;

#pragma unroll 8
    for (int k = 0; k < 64; k++) {
        const float4 a0 = *(const float4*)&XH[k * S_T + mbase];
        const float4 a1 = *(const float4*)&XH[k * S_T + mbase + 4];
        const float4 w  = *(const float4*)&W1s[k * 64 + cbase];
        const unsigned long long A0 = pack_f32x2(a0.x, a0.y);
        const unsigned long long A1 = pack_f32x2(a0.z, a0.w);
        const unsigned long long A2 = pack_f32x2(a1.x, a1.y);
        const unsigned long long A3 = pack_f32x2(a1.z, a1.w);
        const unsigned long long W0 = dup_f32x2(w.x);
        const unsigned long long Wd1 = dup_f32x2(w.y);
        const unsigned long long Wd2 = dup_f32x2(w.z);
        const unsigned long long Wd3 = dup_f32x2(w.w);
        FMA2(acc2[0][0], A0, W0);  FMA2(acc2[0][1], A1, W0);
        FMA2(acc2[0][2], A2, W0);  FMA2(acc2[0][3], A3, W0);
        FMA2(acc2[1][0], A0, Wd1); FMA2(acc2[1][1], A1, Wd1);
        FMA2(acc2[1][2], A2, Wd1); FMA2(acc2[1][3], A3, Wd1);
        FMA2(acc2[2][0], A0, Wd2); FMA2(acc2[2][1], A1, Wd2);
        FMA2(acc2[2][2], A2, Wd2); FMA2(acc2[2][3], A3, Wd2);
        FMA2(acc2[3][0], A0, Wd3); FMA2(acc2[3][1], A1, Wd3);
        FMA2(acc2[3][2], A2, Wd3); FMA2(acc2[3][3], A3, Wd3);
    }

#pragma unroll
    for (int j = 0; j < 4; j++)
#pragma unroll
        for (int ii = 0; ii < 4; ii++)
            unpack_f32x2(acc2[j][ii], acc[j][2 * ii], acc[j][2 * ii + 1]);

    __syncthreads();   // all reads of XH done before overwrite

#pragma unroll
    for (int j = 0; j < 4; j++) {
        const float bj = b1s[cbase + j];
#pragma unroll
        for (int i = 0; i < 8; i++) acc[j][i] = fmaxf(acc[j][i] + bj, 0.f);
        *(float4*)&XH[(cbase + j) * S_T + mbase] =
            make_float4(acc[j][0], acc[j][1], acc[j][2], acc[j][3]);
        *(float4*)&XH[(cbase + j) * S_T + mbase + 4] =
            make_float4(acc[j][4], acc[j][5], acc[j][6], acc[j][7]);
    }
    __syncthreads();

    // ================= Layer 2 =================
#pragma unroll
    for (int j = 0; j < 4; j++)
#pragma unroll
        for (int ii = 0; ii < 4; ii++) acc2[j][ii] = 0ULL;

#pragma unroll 8
    for (int k = 0; k < 64; k++) {
        const float4 a0 = *(const float4*)&XH[k * S_T + mbase];
        const float4 a1 = *(const float4*)&XH[k * S_T + mbase + 4];
        const float4 w  = *(const float4*)&W2s[k * 64 + cbase];
        const unsigned long long A0 = pack_f32x2(a0.x, a0.y);
        const unsigned long long A1 = pack_f32x2(a0.z, a0.w);
        const unsigned long long A2 = pack_f32x2(a1.x, a1.y);
        const unsigned long long A3 = pack_f32x2(a1.z, a1.w);
        const unsigned long long W0 = dup_f32x2(w.x);
        const unsigned long long Wd1 = dup_f32x2(w.y);
        const unsigned long long Wd2 = dup_f32x2(w.z);
        const unsigned long long Wd3 = dup_f32x2(w.w);
        FMA2(acc2[0][0], A0, W0);  FMA2(acc2[0][1], A1, W0);
        FMA2(acc2[0][2], A2, W0);  FMA2(acc2[0][3], A3, W0);
        FMA2(acc2[1][0], A0, Wd1); FMA2(acc2[1][1], A1, Wd1);
        FMA2(acc2[1][2], A2, Wd1); FMA2(acc2[1][3], A3, Wd1);
        FMA2(acc2[2][0], A0, Wd2); FMA2(acc2[2][1], A1, Wd2);
        FMA2(acc2[2][2], A2, Wd2); FMA2(acc2[2][3], A3, Wd2);
        FMA2(acc2[3][0], A0, Wd3); FMA2(acc2[3][1], A1, Wd3);
        FMA2(acc2[3][2], A2, Wd3); FMA2(acc2[3][3], A3, Wd3);
    }

#pragma unroll
    for (int j = 0; j < 4; j++)
#pragma unroll
        for (int ii = 0; ii < 4; ii++)
            unpack_f32x2(acc2[j][ii], acc[j][2 * ii], acc[j][2 * ii + 1]);

#pragma unroll
    for (int j = 0; j < 4; j++) {
        const float bj = b2s[cbase + j];
#pragma unroll
        for (int i = 0; i < 8; i++) acc[j][i] = fmaxf(acc[j][i] + bj, 0.f);
    }

#pragma unroll
    for (int i = 0; i < 8; i++) {
        const int m = m0 + mbase + i;
        if (m < n) {
            if constexpr (sizeof(OutT) == 4) {
                *(float4*)&out[(size_t)m * 64 + cbase] =
                    make_float4(acc[0][i], acc[1][i], acc[2][i], acc[3][i]);
            } else {
                __half2 h01 = __floats2half2_rn(acc[0][i], acc[1][i]);
                __half2 h23 = __floats2half2_rn(acc[2][i], acc[3][i]);
                uint2 u;
                u.x = *(unsigned int*)&h01;
                u.y = *(unsigned int*)&h23;
                *(uint2*)&out[(size_t)m * 64 + cbase] = u;
            }
        }
    }
}

// ---------------------------------------------------------------------------
// Counting sort by dst (R4 champion versions: simple scalar kernels).
// ---------------------------------------------------------------------------
__global__ __launch_bounds__(256) void hist_kernel(const int* __restrict__ dst, int e) {
    int i = blockIdx.x * blockDim.x + threadIdx.x;
    if (i < e) {
        int* addr = &g_hist[dst[i]];
        asm volatile("red.global.add.s32 [%0], 1;" :: "l"(addr) : "memory");
    }
}

__device__ __forceinline__ int warp_incl_scan(int v, int lane) {
#pragma unroll
    for (int d = 1; d < 32; d <<= 1) {
        int t = __shfl_up_sync(0xffffffffu, v, d);
        if (lane >= d) v += t;
    }
    return v;
}

__global__ __launch_bounds__(SCAN_CHUNK) void scan_sums_kernel(int n) {
    __shared__ int wsum[32];
    const int g = blockIdx.x * SCAN_CHUNK + threadIdx.x;
    const int lane = threadIdx.x & 31;
    const int wid = threadIdx.x >> 5;
    int x = (g < n) ? g_hist[g] : 0;
#pragma unroll
    for (int d = 16; d > 0; d >>= 1) x += __shfl_down_sync(0xffffffffu, x, d);
    if (lane == 0) wsum[wid] = x;
    __syncthreads();
    if (wid == 0) {
        int v = wsum[lane];
#pragma unroll
        for (int d = 16; d > 0; d >>= 1) v += __shfl_down_sync(0xffffffffu, v, d);
        if (lane == 0) g_bsum[blockIdx.x] = v;
    }
}

__global__ __launch_bounds__(64) void scan_tops_kernel(int nb, int n) {
    const int lane = threadIdx.x & 31;
    const int i = threadIdx.x;
    __shared__ int w0sum;
    int x = (i < nb) ? g_bsum[i] : 0;
    int incl = warp_incl_scan(x, lane);
    if (i == 31) w0sum = incl;
    __syncthreads();
    int excl = incl - x + ((i >= 32) ? w0sum : 0);
    if (i < nb) g_boff[i] = excl;
    if (i == nb - 1) g_off[n] = excl + x;
}

__global__ __launch_bounds__(SCAN_CHUNK) void scan_final_kernel(int n) {
    __shared__ int wsum[32];
    const int g = blockIdx.x * SCAN_CHUNK + threadIdx.x;
    const int lane = threadIdx.x & 31;
    const int wid = threadIdx.x >> 5;
    int x = (g < n) ? g_hist[g] : 0;
    int incl = warp_incl_scan(x, lane);
    if (lane == 31) wsum[wid] = incl;
    __syncthreads();
    if (wid == 0) wsum[lane] = warp_incl_scan(wsum[lane], lane);
    __syncthreads();
    int excl = incl - x + ((wid > 0) ? wsum[wid - 1] : 0) + g_boff[blockIdx.x];
    if (g < n) {
        g_off[g] = excl;
        g_cursor[g] = excl;
    }
}

__global__ __launch_bounds__(256) void reorder_kernel(
    const int* __restrict__ src, const int* __restrict__ dst, int e)
{
    int i = blockIdx.x * blockDim.x + threadIdx.x;
    if (i < e) {
        int pos = atomicAdd(&g_cursor[dst[i]], 1);
        g_src_sorted[pos] = src[i];
    }
}

// ---------------------------------------------------------------------------
// CSR aggregation: warp per node, fp16 gather, fp32 register accumulation.
// ---------------------------------------------------------------------------
__global__ __launch_bounds__(256) void aggregate_kernel(
    const __half2* __restrict__ m2, float2* __restrict__ z2, int n)
{
    const int warp = (blockIdx.x * 256 + threadIdx.x) >> 5;
    const int lane = threadIdx.x & 31;
    if (warp >= n) return;

    const int s0 = g_off[warp];
    const int s1 = g_off[warp + 1];

    float ax = 0.f, ay = 0.f;
    for (int base = s0; base < s1; base += 32) {
        const int cnt = min(32, s1 - base);
        int si = (lane < cnt) ? g_src_sorted[base + lane] : 0;
#pragma unroll 4
        for (int j = 0; j < cnt; j++) {
            const int s = __shfl_sync(0xffffffffu, si, j);
            const __half2 h = __ldg(&m2[(size_t)s * 32 + lane]);
            const float2 v = __half22float2(h);
            ax += v.x;
            ay += v.y;
        }
    }
    float2 o;
    o.x = ax;
    o.y = ay;
    z2[(size_t)warp * 32 + lane] = o;
}

// ---------------------------------------------------------------------------
extern "C" void kernel_launch(void* const* d_in, const int* in_sizes, int n_in,
                              void* d_out, int out_size) {
    const float* y   = (const float*)d_in[0];
    const int*   src = (const int*)d_in[1];
    const int*   dst = (const int*)d_in[2];
    const float* W1  = (const float*)d_in[3];
    const float* b1  = (const float*)d_in[4];
    const float* W2  = (const float*)d_in[5];
    const float* b2  = (const float*)d_in[6];
    const float* U1  = (const float*)d_in[7];
    const float* c1  = (const float*)d_in[8];
    const float* U2  = (const float*)d_in[9];
    const float* c2  = (const float*)d_in[10];
    float* out = (float*)d_out;

    const int n = in_sizes[0] / D;
    const int e = in_sizes[1];

    __half* mh_ptr = nullptr;
    float*  z_ptr  = nullptr;
    int*    hist_ptr = nullptr;
    cudaGetSymbolAddress((void**)&mh_ptr, g_mh);
    cudaGetSymbolAddress((void**)&z_ptr, g_z);
    cudaGetSymbolAddress((void**)&hist_ptr, g_hist);

    cudaFuncSetAttribute(mlp2_tiled_kernel<__half>,
                         cudaFuncAttributeMaxDynamicSharedMemorySize, SMEM_BYTES);
    cudaFuncSetAttribute(mlp2_tiled_kernel<float>,
                         cudaFuncAttributeMaxDynamicSharedMemorySize, SMEM_BYTES);

    static cudaStream_t s_side = ([] {
        cudaStream_t s;
        cudaStreamCreateWithFlags(&s, cudaStreamNonBlocking);
        return s;
    })();
    static cudaEvent_t ev_fork = ([] {
        cudaEvent_t ev;
        cudaEventCreateWithFlags(&ev, cudaEventDisableTiming);
        return ev;
    })();
    static cudaEvent_t ev_join = ([] {
        cudaEvent_t ev;
        cudaEventCreateWithFlags(&ev, cudaEventDisableTiming);
        return ev;
    })();

    const int mlp_blocks = (n + TILE_M - 1) / TILE_M;
    const int nb = (n + SCAN_CHUNK - 1) / SCAN_CHUNK;

    // ---- fork: sort pipeline on side stream (depends only on src/dst) ----
    cudaEventRecord(ev_fork, (cudaStream_t)0);
    cudaStreamWaitEvent(s_side, ev_fork, 0);

    cudaMemsetAsync(hist_ptr, 0, (size_t)(n + 1) * sizeof(int), s_side);
    hist_kernel<<<(e + 255) / 256, 256, 0, s_side>>>(dst, e);
    scan_sums_kernel<<<nb, SCAN_CHUNK, 0, s_side>>>(n);
    scan_tops_kernel<<<1, 64, 0, s_side>>>(nb, n);
    scan_final_kernel<<<nb, SCAN_CHUNK, 0, s_side>>>(n);
    reorder_kernel<<<(e + 255) / 256, 256, 0, s_side>>>(src, dst, e);
    cudaEventRecord(ev_join, s_side);

    // ---- main stream: edge-MLP message table (fp16 out) ----
    mlp2_tiled_kernel<__half><<<mlp_blocks, 256, SMEM_BYTES>>>(
        y, W1, b1, W2, b2, mh_ptr, n);

    // ---- join, then aggregate + node MLP ----
    cudaStreamWaitEvent((cudaStream_t)0, ev_join, 0);
    {
        const int blocks = (n * 32 + 255) / 256;
        aggregate_kernel<<<blocks, 256>>>((const __half2*)mh_ptr, (float2*)z_ptr, n);
    }
    mlp2_tiled_kernel<float><<<mlp_blocks, 256, SMEM_BYTES>>>(
        z_ptr, U1, c1, U2, c2, out, n);
}

// round 10
// speedup vs baseline: 2.6303x; 1.2313x over previous
#include <cuda_runtime.h>
#include <cuda_fp16.h>
#include <cstdint>

#define D 64
#define NMAX 50000
#define EMAX 1250000
#define TILE_M 128
#define LDX 72            // halves per SMEM row: 144B = 9*16B -> ldmatrix conflict-free
#define SCAN_CHUNK 1024

// ---------------- device scratch (no allocation allowed) ----------------
__device__ __half g_mh[NMAX * D];     // per-node message table (fp16)
__device__ float  g_z[NMAX * D];      // segment-sum result (fp32)
__device__ int    g_hist[NMAX + 1];
__device__ int    g_off[NMAX + 1];    // CSR offsets
__device__ int    g_cursor[NMAX];
__device__ int    g_bsum[64];         // per-chunk sums
__device__ int    g_boff[64];         // per-chunk offsets
__device__ int    g_src_sorted[EMAX];

// SMEM: Xh[128][LDX] fp16 (reused for H1), W1h/W2h[64][LDX] fp16, b1s/b2s[64] f32
#define SMEM_MMA_BYTES (128 * LDX * 2 + 2 * 64 * LDX * 2 + 2 * 64 * 4 + 64)

// ---------------- PTX helpers ----------------
__device__ __forceinline__ uint32_t smem_u32(const void* p) {
    uint32_t a;
    asm("{ .reg .u64 t; cvta.to.shared.u64 t, %1; cvt.u32.u64 %0, t; }"
        : "=r"(a) : "l"(p));
    return a;
}
__device__ __forceinline__ void ldsm_x4(uint32_t& r0, uint32_t& r1,
                                        uint32_t& r2, uint32_t& r3, uint32_t addr) {
    asm volatile("ldmatrix.sync.aligned.m8n8.x4.shared.b16 {%0,%1,%2,%3}, [%4];"
                 : "=r"(r0), "=r"(r1), "=r"(r2), "=r"(r3) : "r"(addr));
}
__device__ __forceinline__ void ldsm_x2t(uint32_t& r0, uint32_t& r1, uint32_t addr) {
    asm volatile("ldmatrix.sync.aligned.m8n8.x2.trans.shared.b16 {%0,%1}, [%2];"
                 : "=r"(r0), "=r"(r1) : "r"(addr));
}
__device__ __forceinline__ void mma16816(float& d0, float& d1, float& d2, float& d3,
                                         uint32_t a0, uint32_t a1, uint32_t a2, uint32_t a3,
                                         uint32_t b0, uint32_t b1) {
    asm volatile(
        "mma.sync.aligned.m16n8k16.row.col.f32.f16.f16.f32 "
        "{%0,%1,%2,%3}, {%4,%5,%6,%7}, {%8,%9}, {%0,%1,%2,%3};"
        : "+f"(d0), "+f"(d1), "+f"(d2), "+f"(d3)
        : "r"(a0), "r"(a1), "r"(a2), "r"(a3), "r"(b0), "r"(b1));
}

// ---------------------------------------------------------------------------
// Tensor-core 2-layer MLP: out = relu(relu(X@W1+b1)@W2+b2).
// fp16 inputs / fp32 accumulate. Block = 256 thr, 128-node tile, warp = 16 rows.
// ---------------------------------------------------------------------------
template <typename OutT>
__global__ __launch_bounds__(256) void mlp2_mma_kernel(
    const float* __restrict__ in,
    const float* __restrict__ W1, const float* __restrict__ b1,
    const float* __restrict__ W2, const float* __restrict__ b2,
    OutT* __restrict__ out, int n)
{
    extern __shared__ __align__(16) char sm_raw[];
    __half* Xh  = (__half*)sm_raw;            // 128 x LDX (reused as H1)
    __half* W1h = Xh + 128 * LDX;             // 64 x LDX
    __half* W2h = W1h + 64 * LDX;             // 64 x LDX
    float*  b1s = (float*)(W2h + 64 * LDX);
    float*  b2s = b1s + 64;

    const int tid  = threadIdx.x;
    const int lane = tid & 31;
    const int wid  = tid >> 5;
    const int m0   = blockIdx.x * TILE_M;

    // ---- stage weights fp32 -> fp16 ----
    for (int p = tid; p < 4096; p += 256) {
        const int r = p >> 6, c = p & 63;
        W1h[r * LDX + c] = __float2half_rn(W1[p]);
        W2h[r * LDX + c] = __float2half_rn(W2[p]);
    }
    if (tid < 64) {
        b1s[tid] = b1[tid];
        b2s[tid] = b2[tid];
    }

    // ---- stage X fp32 -> fp16 (zero-padded past n) ----
    for (int p = tid; p < TILE_M * 16; p += 256) {
        const int r = p >> 4, q = p & 15;
        float4 v = make_float4(0.f, 0.f, 0.f, 0.f);
        if (m0 + r < n) v = ((const float4*)in)[(size_t)(m0 + r) * 16 + q];
        __half2* dp = (__half2*)&Xh[r * LDX + q * 4];
        dp[0] = __floats2half2_rn(v.x, v.y);
        dp[1] = __floats2half2_rn(v.z, v.w);
    }
    __syncthreads();

    const int mrow = wid * 16;
    // A-fragment base address for this thread (ldmatrix x4 lane mapping)
    const uint32_t xrow =
        smem_u32(Xh) + (uint32_t)(((mrow + (lane & 15)) * LDX + (lane >> 4) * 8) << 1);
    const uint32_t w1b = smem_u32(W1h);
    const uint32_t w2b = smem_u32(W2h);
    const int gid = lane >> 2;   // D-fragment row within tile
    const int tig = lane & 3;    // D-fragment col pair

    uint32_t a[4][4];

    // ================= Layer 1 =================
#pragma unroll
    for (int f = 0; f < 4; f++)
        ldsm_x4(a[f][0], a[f][1], a[f][2], a[f][3], xrow + (uint32_t)((f * 16) << 1));

#pragma unroll
    for (int nt = 0; nt < 8; nt++) {
        float d0 = 0.f, d1 = 0.f, d2 = 0.f, d3 = 0.f;
#pragma unroll
        for (int f = 0; f < 4; f++) {
            uint32_t b0r, b1r;
            ldsm_x2t(b0r, b1r,
                     w1b + (uint32_t)(((f * 16 + (lane & 15)) * LDX + nt * 8) << 1));
            mma16816(d0, d1, d2, d3, a[f][0], a[f][1], a[f][2], a[f][3], b0r, b1r);
        }
        const int c = nt * 8 + tig * 2;
        const float2 bb = *(const float2*)&b1s[c];
        const __half2 h01 = __floats2half2_rn(fmaxf(d0 + bb.x, 0.f),
                                              fmaxf(d1 + bb.y, 0.f));
        const __half2 h23 = __floats2half2_rn(fmaxf(d2 + bb.x, 0.f),
                                              fmaxf(d3 + bb.y, 0.f));
        // in-place: this warp only reads rows it writes
        *(__half2*)&Xh[(mrow + gid) * LDX + c]     = h01;
        *(__half2*)&Xh[(mrow + gid + 8) * LDX + c] = h23;
    }
    __syncwarp();

    // ================= Layer 2 =================
#pragma unroll
    for (int f = 0; f < 4; f++)
        ldsm_x4(a[f][0], a[f][1], a[f][2], a[f][3], xrow + (uint32_t)((f * 16) << 1));

#pragma unroll
    for (int nt = 0; nt < 8; nt++) {
        float d0 = 0.f, d1 = 0.f, d2 = 0.f, d3 = 0.f;
#pragma unroll
        for (int f = 0; f < 4; f++) {
            uint32_t b0r, b1r;
            ldsm_x2t(b0r, b1r,
                     w2b + (uint32_t)(((f * 16 + (lane & 15)) * LDX + nt * 8) << 1));
            mma16816(d0, d1, d2, d3, a[f][0], a[f][1], a[f][2], a[f][3], b0r, b1r);
        }
        const int c = nt * 8 + tig * 2;
        const float2 bb = *(const float2*)&b2s[c];
        const float h0 = fmaxf(d0 + bb.x, 0.f);
        const float h1 = fmaxf(d1 + bb.y, 0.f);
        const float h2 = fmaxf(d2 + bb.x, 0.f);
        const float h3 = fmaxf(d3 + bb.y, 0.f);
        const int r0 = m0 + mrow + gid;
        const int r1 = r0 + 8;
        if constexpr (sizeof(OutT) == 4) {
            if (r0 < n) *(float2*)&out[(size_t)r0 * 64 + c] = make_float2(h0, h1);
            if (r1 < n) *(float2*)&out[(size_t)r1 * 64 + c] = make_float2(h2, h3);
        } else {
            if (r0 < n) *(__half2*)&out[(size_t)r0 * 64 + c] = __floats2half2_rn(h0, h1);
            if (r1 < n) *(__half2*)&out[(size_t)r1 * 64 + c] = __floats2half2_rn(h2, h3);
        }
    }
}

// ---------------------------------------------------------------------------
// Counting sort by dst (R4/R9 champion versions).
// ---------------------------------------------------------------------------
__global__ __launch_bounds__(256) void hist_kernel(const int* __restrict__ dst, int e) {
    int i = blockIdx.x * blockDim.x + threadIdx.x;
    if (i < e) {
        int* addr = &g_hist[dst[i]];
        asm volatile("red.global.add.s32 [%0], 1;" :: "l"(addr) : "memory");
    }
}

__device__ __forceinline__ int warp_incl_scan(int v, int lane) {
#pragma unroll
    for (int d = 1; d < 32; d <<= 1) {
        int t = __shfl_up_sync(0xffffffffu, v, d);
        if (lane >= d) v += t;
    }
    return v;
}

__global__ __launch_bounds__(SCAN_CHUNK) void scan_sums_kernel(int n) {
    __shared__ int wsum[32];
    const int g = blockIdx.x * SCAN_CHUNK + threadIdx.x;
    const int lane = threadIdx.x & 31;
    const int wid = threadIdx.x >> 5;
    int x = (g < n) ? g_hist[g] : 0;
#pragma unroll
    for (int d = 16; d > 0; d >>= 1) x += __shfl_down_sync(0xffffffffu, x, d);
    if (lane == 0) wsum[wid] = x;
    __syncthreads();
    if (wid == 0) {
        int v = wsum[lane];
#pragma unroll
        for (int d = 16; d > 0; d >>= 1) v += __shfl_down_sync(0xffffffffu, v, d);
        if (lane == 0) g_bsum[blockIdx.x] = v;
    }
}

__global__ __launch_bounds__(64) void scan_tops_kernel(int nb, int n) {
    const int lane = threadIdx.x & 31;
    const int i = threadIdx.x;
    __shared__ int w0sum;
    int x = (i < nb) ? g_bsum[i] : 0;
    int incl = warp_incl_scan(x, lane);
    if (i == 31) w0sum = incl;
    __syncthreads();
    int excl = incl - x + ((i >= 32) ? w0sum : 0);
    if (i < nb) g_boff[i] = excl;
    if (i == nb - 1) g_off[n] = excl + x;
}

__global__ __launch_bounds__(SCAN_CHUNK) void scan_final_kernel(int n) {
    __shared__ int wsum[32];
    const int g = blockIdx.x * SCAN_CHUNK + threadIdx.x;
    const int lane = threadIdx.x & 31;
    const int wid = threadIdx.x >> 5;
    int x = (g < n) ? g_hist[g] : 0;
    int incl = warp_incl_scan(x, lane);
    if (lane == 31) wsum[wid] = incl;
    __syncthreads();
    if (wid == 0) wsum[lane] = warp_incl_scan(wsum[lane], lane);
    __syncthreads();
    int excl = incl - x + ((wid > 0) ? wsum[wid - 1] : 0) + g_boff[blockIdx.x];
    if (g < n) {
        g_off[g] = excl;
        g_cursor[g] = excl;
    }
}

__global__ __launch_bounds__(256) void reorder_kernel(
    const int* __restrict__ src, const int* __restrict__ dst, int e)
{
    int i = blockIdx.x * blockDim.x + threadIdx.x;
    if (i < e) {
        int pos = atomicAdd(&g_cursor[dst[i]], 1);
        g_src_sorted[pos] = src[i];
    }
}

// ---------------------------------------------------------------------------
// CSR aggregation: warp per node, fp16 gather, fp32 register accumulation.
// ---------------------------------------------------------------------------
__global__ __launch_bounds__(256) void aggregate_kernel(
    const __half2* __restrict__ m2, float2* __restrict__ z2, int n)
{
    const int warp = (blockIdx.x * 256 + threadIdx.x) >> 5;
    const int lane = threadIdx.x & 31;
    if (warp >= n) return;

    const int s0 = g_off[warp];
    const int s1 = g_off[warp + 1];

    float ax = 0.f, ay = 0.f;
    for (int base = s0; base < s1; base += 32) {
        const int cnt = min(32, s1 - base);
        int si = (lane < cnt) ? g_src_sorted[base + lane] : 0;
#pragma unroll 4
        for (int j = 0; j < cnt; j++) {
            const int s = __shfl_sync(0xffffffffu, si, j);
            const __half2 h = __ldg(&m2[(size_t)s * 32 + lane]);
            const float2 v = __half22float2(h);
            ax += v.x;
            ay += v.y;
        }
    }
    float2 o;
    o.x = ax;
    o.y = ay;
    z2[(size_t)warp * 32 + lane] = o;
}

// ---------------------------------------------------------------------------
extern "C" void kernel_launch(void* const* d_in, const int* in_sizes, int n_in,
                              void* d_out, int out_size) {
    const float* y   = (const float*)d_in[0];
    const int*   src = (const int*)d_in[1];
    const int*   dst = (const int*)d_in[2];
    const float* W1  = (const float*)d_in[3];
    const float* b1  = (const float*)d_in[4];
    const float* W2  = (const float*)d_in[5];
    const float* b2  = (const float*)d_in[6];
    const float* U1  = (const float*)d_in[7];
    const float* c1  = (const float*)d_in[8];
    const float* U2  = (const float*)d_in[9];
    const float* c2  = (const float*)d_in[10];
    float* out = (float*)d_out;

    const int n = in_sizes[0] / D;
    const int e = in_sizes[1];

    __half* mh_ptr = nullptr;
    float*  z_ptr  = nullptr;
    int*    hist_ptr = nullptr;
    cudaGetSymbolAddress((void**)&mh_ptr, g_mh);
    cudaGetSymbolAddress((void**)&z_ptr, g_z);
    cudaGetSymbolAddress((void**)&hist_ptr, g_hist);

    cudaFuncSetAttribute(mlp2_mma_kernel<__half>,
                         cudaFuncAttributeMaxDynamicSharedMemorySize, SMEM_MMA_BYTES);
    cudaFuncSetAttribute(mlp2_mma_kernel<float>,
                         cudaFuncAttributeMaxDynamicSharedMemorySize, SMEM_MMA_BYTES);

    static cudaStream_t s_side = ([] {
        cudaStream_t s;
        cudaStreamCreateWithFlags(&s, cudaStreamNonBlocking);
        return s;
    })();
    static cudaEvent_t ev_fork = ([] {
        cudaEvent_t ev;
        cudaEventCreateWithFlags(&ev, cudaEventDisableTiming);
        return ev;
    })();
    static cudaEvent_t ev_join = ([] {
        cudaEvent_t ev;
        cudaEventCreateWithFlags(&ev, cudaEventDisableTiming);
        return ev;
    })();

    const int mlp_blocks = (n + TILE_M - 1) / TILE_M;
    const int nb = (n + SCAN_CHUNK - 1) / SCAN_CHUNK;

    // ---- fork: sort pipeline on side stream (depends only on src/dst) ----
    cudaEventRecord(ev_fork, (cudaStream_t)0);
    cudaStreamWaitEvent(s_side, ev_fork, 0);

    cudaMemsetAsync(hist_ptr, 0, (size_t)(n + 1) * sizeof(int), s_side);
    hist_kernel<<<(e + 255) / 256, 256, 0, s_side>>>(dst, e);
    scan_sums_kernel<<<nb, SCAN_CHUNK, 0, s_side>>>(n);
    scan_tops_kernel<<<1, 64, 0, s_side>>>(nb, n);
    scan_final_kernel<<<nb, SCAN_CHUNK, 0, s_side>>>(n);
    reorder_kernel<<<(e + 255) / 256, 256, 0, s_side>>>(src, dst, e);
    cudaEventRecord(ev_join, s_side);

    // ---- main stream: edge-MLP message table (fp16 out, tensor cores) ----
    mlp2_mma_kernel<__half><<<mlp_blocks, 256, SMEM_MMA_BYTES>>>(
        y, W1, b1, W2, b2, mh_ptr, n);

    // ---- join, then aggregate + node MLP ----
    cudaStreamWaitEvent((cudaStream_t)0, ev_join, 0);
    {
        const int blocks = (n * 32 + 255) / 256;
        aggregate_kernel<<<blocks, 256>>>((const __half2*)mh_ptr, (float2*)z_ptr, n);
    }
    mlp2_mma_kernel<float><<<mlp_blocks, 256, SMEM_MMA_BYTES>>>(
        z_ptr, U1, c1, U2, c2, out, n);
}